// round 16
// baseline (speedup 1.0000x reference)
#include <cuda_runtime.h>
#include <cuda_fp16.h>
#include <cstdint>
#include <cstddef>

// ---------------------------------------------------------------------------
// Problem constants
// ---------------------------------------------------------------------------
constexpr int cB = 4;
constexpr int cL = 1024;
constexpr int cD = 768;
constexpr int cN = 16;
constexpr int cR = 48;
constexpr int cM = cB * cL;          // 4096 rows
constexpr int XPW = cR + 4 * cN;     // 112 true x_proj width
constexpr int XPN = 128;             // padded x_proj width
constexpr int DTK = 64;              // padded dt_proj K (48 -> 64)

// ---------------------------------------------------------------------------
// Scratch (static device globals — no allocation). ALL intermediates half.
// ---------------------------------------------------------------------------
__device__ __half  g_xh  [cM * cD];      // half(x)              (in_proj A)
__device__ __half  g_xinh[cM * cD];      // silu(xz[:, :D])      (x_proj A, dt aux)
__device__ __half  g_zgh [cM * cD];      // silu(xz[:, D:])      (scan gate)
__device__ __half  g_xph [cM * XPN];     // x_in @ x_proj_w      (dt_proj A, scan B/C)
__device__ __half2 g_dtx [cM * cD];      // (dt, dt*xin)         (scan)
__device__ __half  g_ygh [cM * cD];      // half(ys * silu(z))   (out_proj A)
__device__ __half  g_winT[2 * cD * cD];  // in_proj_w^T   [1536][768]
__device__ __half  g_wxpT[XPN * cD];     // x_proj_w^T    [128][768] (rows 112.. = 0)
__device__ __half  g_wdtT[cD * DTK];     // dt_proj_w^T   [768][64]  (cols 48.. = 0)
__device__ __half  g_woT [cD * cD];      // out_proj_w^T  [768][768]

// ---------------------------------------------------------------------------
// Helpers
// ---------------------------------------------------------------------------
__device__ __forceinline__ uint32_t smem_u32(const void* p) {
    uint32_t a;
    asm("{ .reg .u64 t; cvta.to.shared.u64 t, %1; cvt.u32.u64 %0, t; }"
        : "=r"(a) : "l"(p));
    return a;
}
__device__ __forceinline__ float siluf(float x) { return x / (1.0f + __expf(-x)); }
__device__ __forceinline__ float softplusf(float x) {
    return fmaxf(x, 0.0f) + log1pf(__expf(-fabsf(x)));
}
__device__ __forceinline__ void mma_f16(float* c, const uint32_t* a, const uint32_t* b) {
    asm volatile(
        "mma.sync.aligned.m16n8k16.row.col.f32.f16.f16.f32 "
        "{%0,%1,%2,%3}, {%4,%5,%6,%7}, {%8,%9}, {%0,%1,%2,%3};"
        : "+f"(c[0]), "+f"(c[1]), "+f"(c[2]), "+f"(c[3])
        : "r"(a[0]), "r"(a[1]), "r"(a[2]), "r"(a[3]), "r"(b[0]), "r"(b[1]));
}
__device__ __forceinline__ void ldm_x4(uint32_t* r, uint32_t addr) {
    asm volatile("ldmatrix.sync.aligned.m8n8.x4.shared.b16 {%0,%1,%2,%3}, [%4];"
                 : "=r"(r[0]), "=r"(r[1]), "=r"(r[2]), "=r"(r[3]) : "r"(addr));
}
__device__ __forceinline__ void ldm_x2(uint32_t* r, uint32_t addr) {
    asm volatile("ldmatrix.sync.aligned.m8n8.x2.shared.b16 {%0,%1}, [%2];"
                 : "=r"(r[0]), "=r"(r[1]) : "r"(addr));
}
__device__ __forceinline__ void cp16(uint32_t s, const void* g) {
    asm volatile("cp.async.cg.shared.global [%0], [%1], 16;" :: "r"(s), "l"(g));
}
#define CP_COMMIT() asm volatile("cp.async.commit_group;" ::: "memory")
#define CP_WAIT1()  asm volatile("cp.async.wait_group 1;"  ::: "memory")

// ---------------------------------------------------------------------------
// Epilogues (write device globals directly; everything half)
//  0: in_proj split-silu -> xinh / zgh
//  1: x_proj plain       -> xph
//  2: dt_proj            -> dtx = (softplus(v+bias), softplus*xin)
//  3: out_proj bias      -> fp32 out
// ---------------------------------------------------------------------------
template<int EPI>
__device__ __forceinline__ void epi_store(int m, int col, float v,
                                          float* C0, const float* bias, int ldc) {
    if constexpr (EPI == 0) {
        float s = siluf(v);
        if (col < cD) g_xinh[(size_t)m * cD + col] = __float2half_rn(s);
        else          g_zgh [(size_t)m * cD + (col - cD)] = __float2half_rn(s);
    } else if constexpr (EPI == 1) {
        g_xph[(size_t)m * XPN + col] = __float2half_rn(v);
    } else if constexpr (EPI == 2) {
        float dtv = softplusf(v + bias[col]);
        size_t idx = (size_t)m * cD + col;
        float xin = __half2float(g_xinh[idx]);
        g_dtx[idx] = __floats2half2_rn(dtv, dtv * xin);
    } else {
        C0[(size_t)m * ldc + col] = v + bias[col];
    }
}

// ---------------------------------------------------------------------------
// fp16 tensor-core GEMM, cp.async 3-stage pipeline.
// C[M,N] = A[M,K] @ Bw^T, A half [M][lda], Bw half [N][K].
// CTA tile 128x128, 256 threads = 8 warps (2m x 4n), warp tile 64x32, BK=32.
// ---------------------------------------------------------------------------
constexpr int STG_BYTES = 128 * 40 * 2;
constexpr int STAGE     = 2 * STG_BYTES;
constexpr int GSMEM     = 3 * STAGE;       // 61440

template<int EPI>
__global__ void __launch_bounds__(256, 2) gemm_h(
    const __half* __restrict__ A, const __half* __restrict__ Bw,
    float* __restrict__ C0, const float* __restrict__ bias,
    int K, int lda, int ldc)
{
    extern __shared__ __align__(16) char smem[];
    const uint32_t sm0 = smem_u32(smem);

    const int tid  = threadIdx.x;
    const int wid  = tid >> 5;
    const int lane = tid & 31;
    const int g    = lane >> 2;
    const int t    = lane & 3;
    const int mw   = (wid & 1) * 64;
    const int nw   = (wid >> 1) * 32;
    const int m0   = blockIdx.y * 128;
    const int n0   = blockIdx.x * 128;

    float c[4][4][4];
#pragma unroll
    for (int im = 0; im < 4; im++)
#pragma unroll
        for (int in_ = 0; in_ < 4; in_++)
#pragma unroll
            for (int r = 0; r < 4; r++) c[im][in_][r] = 0.0f;

    const int aRow = mw + (lane & 15);
    const int aK   = (lane >> 4) * 8;
    const int bRow = nw + (lane & 7);
    const int bK   = ((lane >> 3) & 1) * 8;

    const __half* Ab = A  + (size_t)m0 * lda;
    const __half* Bb = Bw + (size_t)n0 * K;
    const int nk = K / 32;

    const int cr = tid >> 2, cq = tid & 3;

    auto ISSUE = [&](int kb, int slot) {
        const __half* Ag = Ab + (size_t)kb * 32;
        const __half* Bg = Bb + (size_t)kb * 32;
        uint32_t sA = sm0 + slot * STAGE;
        uint32_t sB = sA + STG_BYTES;
#pragma unroll
        for (int i = 0; i < 2; i++) {
            int r = cr + i * 64;
            uint32_t off = (uint32_t)(r * 40 + cq * 8) * 2;
            cp16(sA + off, Ag + (size_t)r * lda + cq * 8);
            cp16(sB + off, Bg + (size_t)r * K   + cq * 8);
        }
    };

    ISSUE(0, 0); CP_COMMIT();
    if (nk > 1) ISSUE(1, 1);
    CP_COMMIT();

    for (int kb = 0; kb < nk; kb++) {
        CP_WAIT1();
        __syncthreads();

        if (kb + 2 < nk) ISSUE(kb + 2, (kb + 2) % 3);
        CP_COMMIT();

        const int slot = kb % 3;
        const uint32_t bA = sm0 + slot * STAGE;
        const uint32_t bB = bA + STG_BYTES;
#pragma unroll
        for (int ks = 0; ks < 2; ks++) {
            uint32_t af[4][4];
#pragma unroll
            for (int im = 0; im < 4; im++)
                ldm_x4(af[im], bA + ((aRow + im * 16) * 40 + ks * 16 + aK) * 2);
            uint32_t bf[4][2];
#pragma unroll
            for (int in_ = 0; in_ < 4; in_++)
                ldm_x2(bf[in_], bB + ((bRow + in_ * 8) * 40 + ks * 16 + bK) * 2);
#pragma unroll
            for (int in_ = 0; in_ < 4; in_++)
#pragma unroll
                for (int im = 0; im < 4; im++)
                    mma_f16(c[im][in_], af[im], bf[in_]);
        }
    }

#pragma unroll
    for (int im = 0; im < 4; im++) {
        const int row0 = m0 + mw + im * 16 + g;
#pragma unroll
        for (int in_ = 0; in_ < 4; in_++) {
            const int col0 = n0 + nw + in_ * 8 + 2 * t;
            epi_store<EPI>(row0,     col0,     c[im][in_][0], C0, bias, ldc);
            epi_store<EPI>(row0,     col0 + 1, c[im][in_][1], C0, bias, ldc);
            epi_store<EPI>(row0 + 8, col0,     c[im][in_][2], C0, bias, ldc);
            epi_store<EPI>(row0 + 8, col0 + 1, c[im][in_][3], C0, bias, ldc);
        }
    }
}

// ---------------------------------------------------------------------------
// Fused prep: all 4 weight transposes + x f2h in ONE launch.
// Block ranges (256 thr each):
//   [0,1152)      w_in  transpose 48x24
//   [1152,1248)   w_xp  transpose 4x24
//   [1248,1296)   w_dt  transpose 24x2
//   [1296,1872)   w_o   transpose 24x24
//   [1872,4944)   f2h(x) 3072 blocks
// ---------------------------------------------------------------------------
__device__ __forceinline__ void do_transpose(const float* __restrict__ src,
                                             __half* __restrict__ dst,
                                             int Ks, int Ns, int Kp, int Np,
                                             int bx, int by) {
    __shared__ float tsm[32][33];
    const int tx = threadIdx.x & 31;
    const int ty = threadIdx.x >> 5;     // 0..7
    int nb = bx * 32, kb = by * 32;
#pragma unroll
    for (int i = ty; i < 32; i += 8) {
        int k = kb + i, n = nb + tx;
        tsm[i][tx] = (k < Ks && n < Ns) ? src[(size_t)k * Ns + n] : 0.0f;
    }
    __syncthreads();
#pragma unroll
    for (int i = ty; i < 32; i += 8) {
        int n = nb + i, k = kb + tx;
        if (n < Np && k < Kp) dst[(size_t)n * Kp + k] = __float2half_rn(tsm[tx][i]);
    }
}

__global__ void prep_kernel(const float* __restrict__ w_in,
                            const float* __restrict__ w_xp,
                            const float* __restrict__ w_dt,
                            const float* __restrict__ w_o,
                            const float* __restrict__ x) {
    int b = blockIdx.x;
    if (b < 1152) {
        do_transpose(w_in, g_winT, cD, 2 * cD, cD, 2 * cD, b % 48, b / 48);
    } else if (b < 1248) {
        b -= 1152;
        do_transpose(w_xp, g_wxpT, cD, XPW, cD, XPN, b % 4, b / 4);
    } else if (b < 1296) {
        b -= 1248;
        do_transpose(w_dt, g_wdtT, cR, cD, DTK, cD, b % 24, b / 24);
    } else if (b < 1872) {
        b -= 1296;
        do_transpose(w_o, g_woT, cD, cD, cD, cD, b % 24, b / 24);
    } else {
        b -= 1872;
        int i = b * 256 + threadIdx.x;          // float4 index
        if (i < cM * cD / 4) {
            float4 v = *(const float4*)(x + (size_t)i * 4);
            __half2 a = __floats2half2_rn(v.x, v.y);
            __half2 c2 = __floats2half2_rn(v.z, v.w);
            uint2 u;
            u.x = *reinterpret_cast<uint32_t*>(&a);
            u.y = *reinterpret_cast<uint32_t*>(&c2);
            *(uint2*)(g_xh + (size_t)i * 4) = u;
        }
    }
}

// ---------------------------------------------------------------------------
// Sequential scan. Inputs packed half: dtx = (dt, dt*xin), B/C half2 from xph,
// zg predicated to the n==0 output lane. 3 loads per thread per step.
// ---------------------------------------------------------------------------
__global__ __launch_bounds__(128)
void scan_kernel(const float* __restrict__ A_log) {
    const int b = blockIdx.y;
    const int n = threadIdx.x & 15;
    const int d = blockIdx.x * 8 + (threadIdx.x >> 4);

    const float AnegL2e = -__expf(A_log[n]) * 1.4426950408889634f;
    const float ph = (float)n * 0.39269908169872414f;
    float h0 = 0.01f * cosf(ph);
    float h1 = 0.01f * sinf(ph);
    float lgm2;
    {
        float r2 = fmaf(h0, h0, fmaf(h1, h1, 1e-8f));
        asm("lg2.approx.f32 %0, %1;" : "=f"(lgm2) : "f"(r2));
    }

    const size_t iD = (size_t)b * cL * cD + d;
    const size_t iP = (size_t)b * cL * XPN;
    const bool lead = (n == 0);

    struct In { __half2 dtx, Bn, Cn; float zv; };
    auto LOAD = [&](int t) -> In {
        In r;
        size_t jD = iD + (size_t)t * cD;
        const __half* xpr = g_xph + iP + (size_t)t * XPN;
        r.dtx = g_dtx[jD];
        r.Bn  = *(const __half2*)(xpr + cR + 2 * n);
        r.Cn  = *(const __half2*)(xpr + cR + 2 * cN + 2 * n);
        r.zv  = lead ? __half2float(g_zgh[jD]) : 0.0f;
        return r;
    };

    In pre[2];
    pre[0] = LOAD(0);
    pre[1] = LOAD(1);

    for (int t = 0; t < cL; t++) {
        In cur = pre[t & 1];
        if (t + 2 < cL) pre[t & 1] = LOAD(t + 2);

        const float dtv = __low2float(cur.dtx);
        const float xv  = __high2float(cur.dtx);
        const float2 Bn = __half22float2(cur.Bn);
        const float2 Cn = __half22float2(cur.Cn);

        float alpha;
        asm("ex2.approx.f32 %0, %1;" : "=f"(alpha) : "f"(dtv * AnegL2e));
        float q = 0.25f * (1.0f - alpha);

        float s1;
        asm("ex2.approx.f32 %0, %1;" : "=f"(s1) : "f"(q * lgm2));

        h0 = fmaf(s1, h0, Bn.x * xv);
        h1 = fmaf(s1, h1, Bn.y * xv);

        float r2b = fmaf(h0, h0, fmaf(h1, h1, 1e-8f));
        float inv = rsqrtf(r2b);
        float m2  = r2b * inv;
        float th;
        asm("tanh.approx.f32 %0, %1;" : "=f"(th) : "f"(m2));
        float sc = th * inv;
        h0 *= sc;
        h1 *= sc;

        float th2 = fmaf(th, th, 1e-8f);
        asm("lg2.approx.f32 %0, %1;" : "=f"(lgm2) : "f"(th2));

        float yv = fmaf(h0, Cn.x, h1 * Cn.y);
        yv += __shfl_xor_sync(0xffffffffu, yv, 1);
        yv += __shfl_xor_sync(0xffffffffu, yv, 2);
        yv += __shfl_xor_sync(0xffffffffu, yv, 4);
        yv += __shfl_xor_sync(0xffffffffu, yv, 8);
        if (lead) g_ygh[iD + (size_t)t * cD] = __float2half_rn(yv * cur.zv);
    }
}

// ---------------------------------------------------------------------------
// kernel_launch
// inputs: x, in_proj_w, x_proj_w, dt_proj_w, dt_proj_b, out_proj_w, out_proj_b, A_log
// ---------------------------------------------------------------------------
extern "C" void kernel_launch(void* const* d_in, const int* in_sizes, int n_in,
                              void* d_out, int out_size) {
    const float* x     = (const float*)d_in[0];
    const float* w_in  = (const float*)d_in[1];
    const float* w_xp  = (const float*)d_in[2];
    const float* w_dt  = (const float*)d_in[3];
    const float* b_dt  = (const float*)d_in[4];
    const float* w_o   = (const float*)d_in[5];
    const float* b_o   = (const float*)d_in[6];
    const float* A_log = (const float*)d_in[7];
    float* out = (float*)d_out;

    __half *p_xh, *p_xinh, *p_xph, *p_ygh, *p_winT, *p_wxpT, *p_wdtT, *p_woT;
    cudaGetSymbolAddress((void**)&p_xh,   g_xh);
    cudaGetSymbolAddress((void**)&p_xinh, g_xinh);
    cudaGetSymbolAddress((void**)&p_xph,  g_xph);
    cudaGetSymbolAddress((void**)&p_ygh,  g_ygh);
    cudaGetSymbolAddress((void**)&p_winT, g_winT);
    cudaGetSymbolAddress((void**)&p_wxpT, g_wxpT);
    cudaGetSymbolAddress((void**)&p_wdtT, g_wdtT);
    cudaGetSymbolAddress((void**)&p_woT,  g_woT);

    cudaFuncSetAttribute(gemm_h<0>, cudaFuncAttributeMaxDynamicSharedMemorySize, GSMEM);
    cudaFuncSetAttribute(gemm_h<1>, cudaFuncAttributeMaxDynamicSharedMemorySize, GSMEM);
    cudaFuncSetAttribute(gemm_h<2>, cudaFuncAttributeMaxDynamicSharedMemorySize, GSMEM);
    cudaFuncSetAttribute(gemm_h<3>, cudaFuncAttributeMaxDynamicSharedMemorySize, GSMEM);

    // 0) fused prep (weights + x f2h), one launch
    prep_kernel<<<4944, 256>>>(w_in, w_xp, w_dt, w_o, x);

    // 1) in_proj: xinh = silu(x@w[:, :D]), zgh = silu(x@w[:, D:])
    gemm_h<0><<<dim3(12, 32), 256, GSMEM>>>(
        p_xh, p_winT, nullptr, nullptr, cD, cD, 0);

    // 2) x_proj: xph = xin @ xpw
    gemm_h<1><<<dim3(1, 32), 256, GSMEM>>>(
        p_xinh, p_wxpT, nullptr, nullptr, cD, cD, 0);

    // 3) dt_proj (K padded 64): dtx = (softplus(xp@w_dt + b), softplus*xin)
    gemm_h<2><<<dim3(6, 32), 256, GSMEM>>>(
        p_xph, p_wdtT, nullptr, b_dt, DTK, XPN, 0);

    // 4) recurrent scan -> ygh = half(ys * silu(z))
    scan_kernel<<<dim3(cD / 8, cB), 128>>>(A_log);

    // 5) out_proj: out = yg @ w_o + b_o
    gemm_h<3><<<dim3(6, 32), 256, GSMEM>>>(
        p_ygh, p_woT, out, b_o, cD, cD, cD);
}